// round 16
// baseline (speedup 1.0000x reference)
#include <cuda_runtime.h>
#include <cuda_bf16.h>
#include <math.h>
#include <stdint.h>

#define Bb 8
#define Mm 2048
#define Dd 128
#define HDIM 16
#define Vv 32
#define TOK (Bb*Mm)          // 16384
#define P 68                 // smem word pitch for GEMM planes
#define KP 12                // smem word pitch for attention K/V tiles
#define ONES 0x3F803F80u     // bf16x2 (1.0, 1.0)

#define OFF_IN 384
#define OFF_OP 768
#define OFF_LW 896
#define OFF_OW 1024
#define WROWS 1056           // +lw(128)+ow(32); lo planes for rows >= 896

// ----------------------------- scratch ---------------------------------------
__device__ float g_x0[TOK*Dd];
__device__ float g_x1[TOK*Dd];
__device__ uint32_t g_wh[WROWS*64];   // pre-packed bf16 hi planes (all weights)
__device__ uint32_t g_wlo[160*64];    // lo planes for lw (128 rows) + ow (32 rows)
__device__ uint32_t g_ath[TOK*64];    // attention out, packed bf16 pairs
__device__ uint32_t g_qh[TOK*64];     // Q pre-scaled by EXPC
__device__ uint32_t g_kh[TOK*64];
__device__ uint32_t g_vh[TOK*64];
__device__ float g_cos[Mm*64];
__device__ float g_sin[Mm*64];
__device__ float g_part[Bb*128];
__device__ float g_part2[256];
__device__ float g_losspart[128];

// ----------------------------- helpers ----------------------------------------
__device__ __forceinline__ uint32_t s_addr(const void* p) {
    uint32_t a;
    asm("{ .reg .u64 t; cvta.to.shared.u64 t, %1; cvt.u32.u64 %0, t; }"
        : "=r"(a) : "l"(p));
    return a;
}
__device__ __forceinline__ void cpa16(uint32_t saddr, const void* g) {
    asm volatile("cp.async.ca.shared.global [%0], [%1], 16;"
                 :: "r"(saddr), "l"(g));
}
#define CPA_COMMIT asm volatile("cp.async.commit_group;")
#define CPA_WAIT   asm volatile("cp.async.wait_group 0;" ::: "memory")

__device__ __forceinline__ void ldsm4(uint32_t r[4], uint32_t addr) {
    asm volatile("ldmatrix.sync.aligned.m8n8.x4.shared.b16 {%0,%1,%2,%3}, [%4];"
        : "=r"(r[0]), "=r"(r[1]), "=r"(r[2]), "=r"(r[3]) : "r"(addr));
}
__device__ __forceinline__ void ldsm4t(uint32_t r[4], uint32_t addr) {
    asm volatile("ldmatrix.sync.aligned.m8n8.x4.trans.shared.b16 {%0,%1,%2,%3}, [%4];"
        : "=r"(r[0]), "=r"(r[1]), "=r"(r[2]), "=r"(r[3]) : "r"(addr));
}
__device__ __forceinline__ void mma_bf16(float c[4], const uint32_t a[4],
                                         uint32_t b0, uint32_t b1) {
    asm volatile(
        "mma.sync.aligned.m16n8k16.row.col.f32.bf16.bf16.f32 "
        "{%0,%1,%2,%3}, {%4,%5,%6,%7}, {%8,%9}, {%0,%1,%2,%3};"
        : "+f"(c[0]), "+f"(c[1]), "+f"(c[2]), "+f"(c[3])
        : "r"(a[0]), "r"(a[1]), "r"(a[2]), "r"(a[3]), "r"(b0), "r"(b1));
}
__device__ __forceinline__ void bf16_split2(float x, float y,
                                            uint32_t& hi, uint32_t& lo) {
    __nv_bfloat162 hb = __float22bfloat162_rn(make_float2(x, y));
    float2 back = __bfloat1622float2(hb);
    __nv_bfloat162 lb = __float22bfloat162_rn(make_float2(x - back.x, y - back.y));
    hi = *(uint32_t*)&hb;
    lo = *(uint32_t*)&lb;
}
__device__ __forceinline__ uint32_t bf16_pack2(float x, float y) {
    __nv_bfloat162 hb = __float22bfloat162_rn(make_float2(x, y));
    return *(uint32_t*)&hb;
}
__device__ __forceinline__ float2 bf2_unpack(uint32_t w) {
    __nv_bfloat162 t;
    *(uint32_t*)&t = w;
    return __bfloat1622float2(t);
}
__device__ __forceinline__ void stage4(uint32_t* H, uint32_t* L, int idx,
                                       float a, float b, float c, float d) {
    uint32_t h0, l0, h1, l1;
    bf16_split2(a, b, h0, l0);
    bf16_split2(c, d, h1, l1);
    H[idx] = h0; H[idx + 1] = h1;
    L[idx] = l0; L[idx + 1] = l1;
}
__device__ __forceinline__ void stageH(uint32_t* H, int idx,
                                       float a, float b, float c, float d) {
    H[idx]     = bf16_pack2(a, b);
    H[idx + 1] = bf16_pack2(c, d);
}
#define EXPC 0.36067376022224085f
__device__ __forceinline__ float pexp(float t) {
    float r; asm("ex2.approx.f32 %0, %1;" : "=f"(r) : "f"(t));
    return r;
}

#define MMA6(accE, accO, ah, al, bh, bl)            \
    do {                                            \
        mma_bf16(accE, ah, (bh)[0], (bh)[2]);       \
        mma_bf16(accE, al, (bh)[0], (bh)[2]);       \
        mma_bf16(accE, ah, (bl)[0], (bl)[2]);       \
        mma_bf16(accO, ah, (bh)[1], (bh)[3]);       \
        mma_bf16(accO, al, (bh)[1], (bh)[3]);       \
        mma_bf16(accO, ah, (bl)[1], (bl)[3]);       \
    } while (0)

#define MMA2(accE, accO, ah, bh)                    \
    do {                                            \
        mma_bf16(accE, ah, (bh)[0], (bh)[2]);       \
        mma_bf16(accO, ah, (bh)[1], (bh)[3]);       \
    } while (0)

// =============================================================================
// Pre-pack weights to bf16 planes (hi for all; hi+lo for lw/ow)
// =============================================================================
__global__ void __launch_bounds__(256) k_prep(
    const float* __restrict__ Wq, const float* __restrict__ Wk,
    const float* __restrict__ Wv, const float* __restrict__ inw,
    const float* __restrict__ opw, const float* __restrict__ lw,
    const float* __restrict__ ow)
{
    int wid = blockIdx.x * 256 + threadIdx.x;
    if (wid >= WROWS * 64) return;
    int row = wid >> 6, col = wid & 63;
    const float* src;
    int r = row;
    if      (r < 128)  { src = Wq; }
    else if (r < 256)  { src = Wk;  r -= 128; }
    else if (r < 384)  { src = Wv;  r -= 256; }
    else if (r < 768)  { src = inw; r -= 384; }
    else if (r < 896)  { src = opw; r -= 768; }
    else if (r < 1024) { src = lw;  r -= 896; }
    else               { src = ow;  r -= 1024; }
    float2 v = *(const float2*)(src + (size_t)r * 128 + col * 2);
    if (row < OFF_LW) {
        g_wh[wid] = bf16_pack2(v.x, v.y);
    } else {
        uint32_t h, l;
        bf16_split2(v.x, v.y, h, l);
        g_wh[wid] = h;
        g_wlo[(size_t)(row - OFF_LW) * 64 + col] = l;
    }
}

// =============================================================================
// Fused embed (+ssq partials) + RoPE tables (powf hoisted). grid (8, 136)
// =============================================================================
__global__ void __launch_bounds__(256) k_embed(const int* __restrict__ idx,
                                               const float* __restrict__ emb) {
    int tid = threadIdx.x;
    if (blockIdx.y >= 128) {
        int rb = blockIdx.x * 8 + (blockIdx.y - 128);
        int i = tid & 63;                     // constant across e
        int pos0 = rb * 32 + (tid >> 6);      // step 4 per e
        float base = powf(10000.0f, -2.0f * ((float)i - 1.0f) / 128.0f);
        #pragma unroll
        for (int e = 0; e < 8; e++) {
            int pos = pos0 + e * 4;
            float ang = (float)pos * base;
            float s, c;
            sincosf(ang, &s, &c);
            g_cos[pos * 64 + i] = c;
            g_sin[pos * 64 + i] = s;
        }
        return;
    }
    int b   = blockIdx.x;
    int seg = blockIdx.y;
    int tok0 = seg * 16;
    float ss = 0.f;
    #pragma unroll
    for (int e = 0; e < 8; e++) {
        int li = tid + e * 256;
        int t  = tok0 + (li >> 7);
        int d  = li & 127;
        int row = idx[b*Mm + t];
        float vv = emb[row*Dd + d];
        g_x0[((size_t)(b*Mm + t))*Dd + d] = vv;
        ss += vv * vv;
    }
    __shared__ float red[256];
    red[tid] = ss; __syncthreads();
    for (int s = 128; s > 0; s >>= 1) {
        if (tid < s) red[tid] += red[tid + s];
        __syncthreads();
    }
    if (tid == 0) g_part[b*128 + seg] = red[0];
}

__device__ __forceinline__ void inv_reduce(const float* part, int bb,
                                           int lane, float* sinv) {
    float v = part[bb*128 + lane]      + part[bb*128 + lane + 32]
            + part[bb*128 + lane + 64] + part[bb*128 + lane + 96];
    #pragma unroll
    for (int off = 16; off; off >>= 1) v += __shfl_xor_sync(0xffffffffu, v, off);
    if (lane == 0) *sinv = 512.0f / sqrtf(v);
}

// =============================================================================
// Fused QKV — 64-row CTAs, 128 threads, 3 CTAs/SM. grid (256, 3)
// =============================================================================
__global__ void __launch_bounds__(128, 3) k_qkv(
    const float* __restrict__ x0, const float* __restrict__ rms,
    const float* __restrict__ inb,
    uint32_t* __restrict__ qh_, uint32_t* __restrict__ kh_,
    uint32_t* __restrict__ vh_)
{
    extern __shared__ uint32_t smw[];
    uint32_t* Ah = smw;
    uint32_t* Wh = Ah + 64 * P;
    float* bias_s = (float*)(Wh + 128 * P);
    __shared__ float sinv;

    int which = blockIdx.y;
    uint32_t* Oh = (which == 0) ? qh_ : ((which == 1) ? kh_ : vh_);
    const uint32_t* W1 = g_wh + (size_t)(which * 128) * 64;
    const uint32_t* W2 = g_wh + (size_t)(OFF_IN + which * 128) * 64;
    float oscale = (which == 0) ? EXPC : 1.0f;

    int tid = threadIdx.x;
    int rowBase = blockIdx.x * 64;
    if (tid < 32) inv_reduce(g_part, rowBase >> 11, tid, &sinv);
    bias_s[tid] = inb[which * 128 + tid];

    uint32_t sAh = s_addr(Ah), sWh = s_addr(Wh);

    #pragma unroll
    for (int i = 0; i < 16; i++) {
        int f = tid + i * 128;
        int row = f >> 4, c = (f & 15) * 4;
        cpa16(sWh + ((uint32_t)row * P + c) * 4, W1 + (size_t)row * 64 + c);
    }
    CPA_COMMIT;
    __syncthreads();
    float inv = sinv;

    #pragma unroll
    for (int i = 0; i < 16; i++) {
        int f = tid + i * 128;
        int row = f >> 5, q4 = f & 31;
        int m = (rowBase + row) & (Mm - 1);
        float4 xv = *(const float4*)(x0 + (size_t)(rowBase + row) * 128 + q4 * 4);
        float4 sv = *(const float4*)(rms + (size_t)m * 128 + q4 * 4);
        stageH(Ah, row * P + q4 * 2,
               xv.x * inv * sv.x, xv.y * inv * sv.y,
               xv.z * inv * sv.z, xv.w * inv * sv.w);
    }
    CPA_WAIT;
    __syncthreads();

    int w = tid >> 5, lane = tid & 31, g = lane >> 2, tg = lane & 3;
    int r0 = w * 16 + g, r1 = r0 + 8;
    int lrow = lane & 15;
    int lcol = (lane >> 4) * 4;
    uint32_t aoff = ((uint32_t)(w * 16 + lrow) * P + lcol) * 4;
    uint32_t boff = ((uint32_t)lrow * P + lcol) * 4;
    uint32_t adA = sAh + aoff;
    uint32_t adW = sWh + boff;

    float acc[16][4];
    #pragma unroll
    for (int nt = 0; nt < 16; nt++)
        #pragma unroll
        for (int e = 0; e < 4; e++) acc[nt][e] = 0.f;

    #pragma unroll
    for (int kg = 0; kg < 8; kg++) {
        uint32_t ah[4];
        ldsm4(ah, adA + kg * 32);
        #pragma unroll
        for (int ntp = 0; ntp < 8; ntp++) {
            uint32_t bh[4];
            ldsm4(bh, adW + (uint32_t)ntp * (16 * P * 4) + kg * 32);
            MMA2(acc[2*ntp], acc[2*ntp+1], ah, bh);
        }
    }

    int m0 = (rowBase + r0) & (Mm - 1), m1 = (rowBase + r1) & (Mm - 1);
    #pragma unroll
    for (int nt = 0; nt < 16; nt++) {
        int i = nt * 4 + tg;
        float c0 = g_cos[m0 * 64 + i], s0 = g_sin[m0 * 64 + i];
        float c1 = g_cos[m1 * 64 + i], s1 = g_sin[m1 * 64 + i];
        float te = acc[nt][0], to = acc[nt][1];
        acc[nt][0] =  te * c0 + to * s0;
        acc[nt][1] = -te * s0 + to * c0;
        te = acc[nt][2]; to = acc[nt][3];
        acc[nt][2] =  te * c1 + to * s1;
        acc[nt][3] = -te * s1 + to * c1;
    }

    uint32_t a2h[8][4];
    #pragma unroll
    for (int kg = 0; kg < 8; kg++) {
        a2h[kg][0] = bf16_pack2(acc[2*kg][0],   acc[2*kg][1]);
        a2h[kg][1] = bf16_pack2(acc[2*kg][2],   acc[2*kg][3]);
        a2h[kg][2] = bf16_pack2(acc[2*kg+1][0], acc[2*kg+1][1]);
        a2h[kg][3] = bf16_pack2(acc[2*kg+1][2], acc[2*kg+1][3]);
    }
    __syncthreads();

    #pragma unroll
    for (int i = 0; i < 16; i++) {
        int f = tid + i * 128;
        int row = f >> 4, c = (f & 15) * 4;
        cpa16(sWh + ((uint32_t)row * P + c) * 4, W2 + (size_t)row * 64 + c);
    }
    CPA_COMMIT; CPA_WAIT;
    __syncthreads();

    #pragma unroll
    for (int nt = 0; nt < 16; nt++)
        #pragma unroll
        for (int e = 0; e < 4; e++) acc[nt][e] = 0.f;

    #pragma unroll
    for (int kg = 0; kg < 8; kg++) {
        #pragma unroll
        for (int ntp = 0; ntp < 8; ntp++) {
            uint32_t bh[4];
            ldsm4(bh, adW + (uint32_t)ntp * (16 * P * 4) + kg * 32);
            MMA2(acc[2*ntp], acc[2*ntp+1], a2h[kg], bh);
        }
    }

    int grow0 = rowBase + r0, grow1 = rowBase + r1;
    #pragma unroll
    for (int nt = 0; nt < 16; nt++) {
        int col = nt * 8 + 2 * tg;
        float v0 = (acc[nt][0] + bias_s[col])     * oscale;
        float v1 = (acc[nt][1] + bias_s[col + 1]) * oscale;
        float v2 = (acc[nt][2] + bias_s[col])     * oscale;
        float v3 = (acc[nt][3] + bias_s[col + 1]) * oscale;
        Oh[(size_t)grow0 * 64 + nt * 4 + tg] = bf16_pack2(v0, v1);
        Oh[(size_t)grow1 * 64 + nt * 4 + tg] = bf16_pack2(v2, v3);
    }
}

// =============================================================================
// Flash attention — round-15 (best) version, unchanged
// =============================================================================
__device__ __forceinline__ void attn_load_tile(uint32_t* KVbuf, int tokbase,
                                               int h, int kb, int tid) {
    #pragma unroll
    for (int i = 0; i < 2; i++) {
        int s = tid + i * 256;
        int arr = s >> 8;
        int rem = s & 255;
        int key = rem >> 1, hf = rem & 1;
        const uint32_t* src = (arr == 0) ? g_kh : g_vh;
        src += (size_t)(tokbase + kb + key) * 64 + h * 8 + hf * 4;
        cpa16(s_addr(KVbuf + arr * (128 * KP) + key * KP + hf * 4), src);
    }
    CPA_COMMIT;
}

__global__ void __launch_bounds__(256, 3) k_attn_mma() {
    int bid = blockIdx.x;
    int qt = 15 - (bid >> 6);
    int bh = bid & 63;
    int b = bh >> 3, h = bh & 7;
    int tid = threadIdx.x;
    int w = tid >> 5, lane = tid & 31;
    int g = lane >> 2, tg = lane & 3;
    int tokbase = b * Mm;
    int qBase = qt * 128 + w * 16;
    int diag = qBase >> 6;

    __shared__ __align__(16) uint32_t KV[2][2 * 128 * KP];

    uint32_t qh[4];
    {
        const uint32_t* ph = g_qh + (size_t)(tokbase + qBase) * 64 + h * 8;
        qh[0] = ph[(size_t)g * 64 + tg];
        qh[1] = ph[(size_t)(g + 8) * 64 + tg];
        qh[2] = ph[(size_t)g * 64 + tg + 4];
        qh[3] = ph[(size_t)(g + 8) * 64 + tg + 4];
    }

    int lrow = lane & 15;
    int lcol = (lane >> 4) * 4;
    uint32_t kvoff = ((uint32_t)lrow * KP + lcol) * 4;

    float o[2][4];
    #pragma unroll
    for (int t = 0; t < 2; t++)
        #pragma unroll
        for (int e = 0; e < 4; e++) o[t][e] = 0.f;
    float lacc[4] = {0.f, 0.f, 0.f, 0.f};

    int q0 = qBase + g;
    int q1 = qBase + g + 8;

    int nkt = qt + 1;
    attn_load_tile(KV[0], tokbase, h, 0, tid);

    for (int kt = 0; kt < nkt; kt++) {
        int buf = kt & 1;
        CPA_WAIT;
        __syncthreads();
        if (kt + 1 < nkt) attn_load_tile(KV[buf ^ 1], tokbase, h, (kt + 1) * 128, tid);
        uint32_t base = s_addr(KV[buf]);

        #pragma unroll
        for (int half = 0; half < 2; half++) {
            int j2 = kt * 2 + half;
            if (j2 > diag) continue;
            uint32_t adK = base + (uint32_t)half * (64 * KP * 4) + kvoff;
            uint32_t adV = base + (128 * KP * 4) + (uint32_t)half * (64 * KP * 4) + kvoff;

            float s[8][4];
            #pragma unroll
            for (int ntp = 0; ntp < 4; ntp++) {
                #pragma unroll
                for (int e = 0; e < 4; e++) { s[2*ntp][e] = 0.f; s[2*ntp+1][e] = 0.f; }
                uint32_t bh_[4];
                ldsm4(bh_, adK + (uint32_t)ntp * (16 * KP * 4));
                mma_bf16(s[2*ntp],   qh, bh_[0], bh_[2]);
                mma_bf16(s[2*ntp+1], qh, bh_[1], bh_[3]);
            }

            uint32_t pk[8][2];
            if (j2 < diag) {
                #pragma unroll
                for (int nt = 0; nt < 8; nt++) {
                    pk[nt][0] = bf16_pack2(pexp(s[nt][0]), pexp(s[nt][1]));
                    pk[nt][1] = bf16_pack2(pexp(s[nt][2]), pexp(s[nt][3]));
                }
            } else {
                int kbd = j2 * 64;
                #pragma unroll
                for (int nt = 0; nt < 8; nt++) {
                    int kc = kbd + nt * 8 + 2 * tg;
                    float t0 = (kc     <= q0) ? s[nt][0] : -1e30f;
                    float t1 = (kc + 1 <= q0) ? s[nt][1] : -1e30f;
                    float t2 = (kc     <= q1) ? s[nt][2] : -1e30f;
                    float t3 = (kc + 1 <= q1) ? s[nt][3] : -1e30f;
                    pk[nt][0] = bf16_pack2(pexp(t0), pexp(t1));
                    pk[nt][1] = bf16_pack2(pexp(t2), pexp(t3));
                }
            }

            #pragma unroll
            for (int kg = 0; kg < 4; kg++) {
                uint32_t ah[4] = { pk[2*kg][0], pk[2*kg][1], pk[2*kg+1][0], pk[2*kg+1][1] };
                uint32_t bh_[4];
                ldsm4t(bh_, adV + (uint32_t)kg * (16 * KP * 4));
                mma_bf16(o[0], ah, bh_[0], bh_[1]);
                mma_bf16(o[1], ah, bh_[2], bh_[3]);
                mma_bf16(lacc, ah, ONES, ONES);
            }
        }
    }

    float i0 = 1.f / lacc[0], i1 = 1.f / lacc[2];

    #pragma unroll
    for (int t = 0; t < 2; t++) {
        int wrd = h * 8 + t * 4 + tg;
        g_ath[(size_t)(tokbase + q0) * 64 + wrd] = bf16_pack2(o[t][0] * i0, o[t][1] * i0);
        g_ath[(size_t)(tokbase + q1) * 64 + wrd] = bf16_pack2(o[t][2] * i1, o[t][3] * i1);
    }
}

// =============================================================================
// Fused out_proj — unchanged (round 15)
// =============================================================================
__global__ void __launch_bounds__(128, 3) k_oproj(
    const float* __restrict__ opb, const float* __restrict__ x0,
    const float* __restrict__ rms, float* __restrict__ x1)
{
    extern __shared__ uint32_t smw[];
    uint32_t* Ah = smw;
    uint32_t* Wh = Ah + 64 * P;
    float* bias_s = (float*)(Wh + 128 * P);
    float* red = bias_s + 128;
    __shared__ float sinv;

    int tid = threadIdx.x;
    int rowBase = blockIdx.x * 64;
    if (tid < 32) inv_reduce(g_part, rowBase >> 11, tid, &sinv);
    bias_s[tid] = opb[tid];

    uint32_t sAh = s_addr(Ah), sWh = s_addr(Wh);
    const uint32_t* Wsrc = g_wh + (size_t)OFF_OP * 64;

    #pragma unroll
    for (int i = 0; i < 8; i++) {
        int f = tid + i * 128;
        int row = f >> 4, c = (f & 15) * 4;
        cpa16(sAh + ((uint32_t)row * P + c) * 4,
              g_ath + (size_t)(rowBase + row) * 64 + c);
    }
    #pragma unroll
    for (int i = 0; i < 16; i++) {
        int f = tid + i * 128;
        int row = f >> 4, c = (f & 15) * 4;
        cpa16(sWh + ((uint32_t)row * P + c) * 4, Wsrc + (size_t)row * 64 + c);
    }
    CPA_COMMIT; CPA_WAIT;
    __syncthreads();
    float inv = sinv;

    int w = tid >> 5, lane = tid & 31, g = lane >> 2, tg = lane & 3;
    int r0 = w * 16 + g, r1 = r0 + 8;
    int lrow = lane & 15;
    int lcol = (lane >> 4) * 4;
    uint32_t aoff = ((uint32_t)(w * 16 + lrow) * P + lcol) * 4;
    uint32_t boff = ((uint32_t)lrow * P + lcol) * 4;
    uint32_t adA = sAh + aoff;
    uint32_t adW = sWh + boff;

    float acc[16][4];
    #pragma unroll
    for (int nt = 0; nt < 16; nt++)
        #pragma unroll
        for (int e = 0; e < 4; e++) acc[nt][e] = 0.f;

    #pragma unroll
    for (int kg = 0; kg < 8; kg++) {
        uint32_t ah[4];
        ldsm4(ah, adA + kg * 32);
        #pragma unroll
        for (int ntp = 0; ntp < 8; ntp++) {
            uint32_t bh[4];
            ldsm4(bh, adW + (uint32_t)ntp * (16 * P * 4) + kg * 32);
            MMA2(acc[2*ntp], acc[2*ntp+1], ah, bh);
        }
    }

    int grow0 = rowBase + r0, grow1 = rowBase + r1;
    int m0 = grow0 & (Mm - 1), m1 = grow1 & (Mm - 1);
    float ssq = 0.f;
    #pragma unroll
    for (int nt = 0; nt < 16; nt++) {
        int col = nt * 8 + 2 * tg;
        float2 xa = *(const float2*)(x0 + (size_t)grow0 * 128 + col);
        float2 sa = *(const float2*)(rms + (size_t)m0 * 128 + col);
        float2 xb = *(const float2*)(x0 + (size_t)grow1 * 128 + col);
        float2 sb = *(const float2*)(rms + (size_t)m1 * 128 + col);
        float v0 = acc[nt][0] + bias_s[col]     + xa.x * inv * sa.x;
        float v1 = acc[nt][1] + bias_s[col + 1] + xa.y * inv * sa.y;
        float v2 = acc[nt][2] + bias_s[col]     + xb.x * inv * sb.x;
        float v3 = acc[nt][3] + bias_s[col + 1] + xb.y * inv * sb.y;
        float2 o0; o0.x = v0; o0.y = v1;
        float2 o1; o1.x = v2; o1.y = v3;
        *(float2*)(x1 + (size_t)grow0 * 128 + col) = o0;
        *(float2*)(x1 + (size_t)grow1 * 128 + col) = o1;
        ssq += v0 * v0 + v1 * v1 + v2 * v2 + v3 * v3;
    }

    red[tid] = ssq;
    __syncthreads();
    for (int s = 64; s > 0; s >>= 1) {
        if (tid < s) red[tid] += red[tid + s];
        __syncthreads();
    }
    if (tid == 0) g_part2[blockIdx.x] = red[0];
}

// =============================================================================
// Fused MLP + logits + loss partials (3-term; weights via pre-packed planes)
// =============================================================================
__global__ void __launch_bounds__(256, 1) k_mlp(
    const float* __restrict__ x1, const float* __restrict__ rms,
    const float* __restrict__ lb, const float* __restrict__ ob,
    const int* __restrict__ tgt, float* __restrict__ out)
{
    extern __shared__ uint32_t smw[];
    uint32_t* Ah = smw;
    uint32_t* Al = Ah + 128 * P;
    uint32_t* Wh = Al + 128 * P;
    uint32_t* Wl = Wh + 128 * P;
    float* biasl = (float*)(Wl + 128 * P);
    float* biaso = biasl + 128;
    float* red   = biaso + 32;
    __shared__ float sinv;

    int tid = threadIdx.x;
    int rowBase = blockIdx.x * 128;
    int lane = tid & 31;
    if (tid < 32) {
        int bb = rowBase >> 11;
        float v = g_part2[bb * 32 + lane];
        #pragma unroll
        for (int off = 16; off; off >>= 1) v += __shfl_xor_sync(0xffffffffu, v, off);
        if (lane == 0) sinv = 512.0f / sqrtf(v);
    }
    if (tid < 128) biasl[tid] = lb[tid];
    if (tid >= 128 && tid < 160) biaso[tid - 128] = ob[tid - 128];

    uint32_t sAh = s_addr(Ah), sAl = s_addr(Al);
    uint32_t sWh = s_addr(Wh), sWl = s_addr(Wl);

    // W = lw hi/lo planes via cp.async
    {
        const uint32_t* srcWh = g_wh + (size_t)OFF_LW * 64;
        const uint32_t* srcWl = g_wlo;
        #pragma unroll
        for (int i = 0; i < 8; i++) {
            int f = tid + i * 256;
            int row = f >> 4, c = (f & 15) * 4;
            uint32_t so = ((uint32_t)row * P + c) * 4;
            size_t go = (size_t)row * 64 + c;
            cpa16(sWh + so, srcWh + go);
            cpa16(sWl + so, srcWl + go);
        }
        CPA_COMMIT;
    }
    __syncthreads();
    float inv = sinv;

    #pragma unroll
    for (int i = 0; i < 16; i++) {
        int f = tid + i * 256;
        int row = f >> 5, q4 = f & 31;
        int m = (rowBase + row) & (Mm - 1);
        float4 xv = *(const float4*)(x1 + (size_t)(rowBase + row) * 128 + q4 * 4);
        float4 sv = *(const float4*)(rms + (size_t)m * 128 + q4 * 4);
        stage4(Ah, Al, row * P + q4 * 2,
               xv.x * inv * sv.x, xv.y * inv * sv.y,
               xv.z * inv * sv.z, xv.w * inv * sv.w);
    }
    CPA_WAIT;
    __syncthreads();

    int w = tid >> 5, g = lane >> 2, tg = lane & 3;
    int r0 = w * 16 + g, r1 = r0 + 8;
    int lrow = lane & 15;
    int lcol = (lane >> 4) * 4;
    uint32_t aoff = ((uint32_t)(w * 16 + lrow) * P + lcol) * 4;
    uint32_t boff = ((uint32_t)lrow * P + lcol) * 4;
    uint32_t adA_h = sAh + aoff, adA_l = sAl + aoff;
    uint32_t adW_h = sWh + boff, adW_l = sWl + boff;

    float acc[16][4];
    #pragma unroll
    for (int nt = 0; nt < 16; nt++)
        #pragma unroll
        for (int e = 0; e < 4; e++) acc[nt][e] = 0.f;

    #pragma unroll
    for (int kg = 0; kg < 8; kg++) {
        uint32_t ah[4], al[4];
        ldsm4(ah, adA_h + kg * 32);
        ldsm4(al, adA_l + kg * 32);
        #pragma unroll
        for (int ntp = 0; ntp < 8; ntp++) {
            uint32_t bh[4], bl[4];
            ldsm4(bh, adW_h + (uint32_t)ntp * (16 * P * 4) + kg * 32);
            ldsm4(bl, adW_l + (uint32_t)ntp * (16 * P * 4) + kg * 32);
            MMA6(acc[2*ntp], acc[2*ntp+1], ah, al, bh, bl);
        }
    }

    #pragma unroll
    for (int nt = 0; nt < 16; nt++) {
        int wrd = nt * 4 + tg;
        int col = nt * 8 + 2 * tg;
        float2 x2a_h = bf2_unpack(Ah[r0 * P + wrd]);
        float2 x2a_l = bf2_unpack(Al[r0 * P + wrd]);
        float2 x2b_h = bf2_unpack(Ah[r1 * P + wrd]);
        float2 x2b_l = bf2_unpack(Al[r1 * P + wrd]);
        acc[nt][0] = (x2a_h.x + x2a_l.x) + fmaxf(acc[nt][0] + biasl[col],     0.f);
        acc[nt][1] = (x2a_h.y + x2a_l.y) + fmaxf(acc[nt][1] + biasl[col + 1], 0.f);
        acc[nt][2] = (x2b_h.x + x2b_l.x) + fmaxf(acc[nt][2] + biasl[col],     0.f);
        acc[nt][3] = (x2b_h.y + x2b_l.y) + fmaxf(acc[nt][3] + biasl[col + 1], 0.f);
    }

    uint32_t a2h[8][4], a2l[8][4];
    #pragma unroll
    for (int kg = 0; kg < 8; kg++) {
        bf16_split2(acc[2*kg][0],   acc[2*kg][1],   a2h[kg][0], a2l[kg][0]);
        bf16_split2(acc[2*kg][2],   acc[2*kg][3],   a2h[kg][1], a2l[kg][1]);
        bf16_split2(acc[2*kg+1][0], acc[2*kg+1][1], a2h[kg][2], a2l[kg][2]);
        bf16_split2(acc[2*kg+1][2], acc[2*kg+1][3], a2h[kg][3], a2l[kg][3]);
    }
    __syncthreads();

    // ow hi/lo planes via cp.async (32 rows)
    {
        const uint32_t* srcOh = g_wh + (size_t)OFF_OW * 64;
        const uint32_t* srcOl = g_wlo + (size_t)128 * 64;
        #pragma unroll
        for (int i = 0; i < 2; i++) {
            int f = tid + i * 256;
            int row = f >> 4, c = (f & 15) * 4;
            uint32_t so = ((uint32_t)row * P + c) * 4;
            size_t go = (size_t)row * 64 + c;
            cpa16(sWh + so, srcOh + go);
            cpa16(sWl + so, srcOl + go);
        }
        CPA_COMMIT; CPA_WAIT;
    }
    __syncthreads();

    int grow0 = rowBase + r0, grow1 = rowBase + r1;
    float L[4][4];
    #pragma unroll
    for (int nt = 0; nt < 4; nt++)
        #pragma unroll
        for (int e = 0; e < 4; e++) L[nt][e] = 0.f;

    #pragma unroll
    for (int kg = 0; kg < 8; kg++) {
        #pragma unroll
        for (int ntp = 0; ntp < 2; ntp++) {
            uint32_t bh[4], bl[4];
            ldsm4(bh, adW_h + (uint32_t)ntp * (16 * P * 4) + kg * 32);
            ldsm4(bl, adW_l + (uint32_t)ntp * (16 * P * 4) + kg * 32);
            MMA6(L[2*ntp], L[2*ntp+1], a2h[kg], a2l[kg], bh, bl);
        }
    }

    #pragma unroll
    for (int nt = 0; nt < 4; nt++) {
        int col = nt * 8 + 2 * tg;
        L[nt][0] += biaso[col];
        L[nt][1] += biaso[col + 1];
        L[nt][2] += biaso[col];
        L[nt][3] += biaso[col + 1];
        float2 o0; o0.x = L[nt][0]; o0.y = L[nt][1];
        float2 o1; o1.x = L[nt][2]; o1.y = L[nt][3];
        *(float2*)(out + (size_t)grow0 * 32 + col) = o0;
        *(float2*)(out + (size_t)grow1 * 32 + col) = o1;
    }

    float mx0 = -1e30f, mx1 = -1e30f;
    #pragma unroll
    for (int nt = 0; nt < 4; nt++) {
        mx0 = fmaxf(mx0, fmaxf(L[nt][0], L[nt][1]));
        mx1 = fmaxf(mx1, fmaxf(L[nt][2], L[nt][3]));
    }
    mx0 = fmaxf(mx0, __shfl_xor_sync(0xffffffffu, mx0, 1));
    mx0 = fmaxf(mx0, __shfl_xor_sync(0xffffffffu, mx0, 2));
    mx1 = fmaxf(mx1, __shfl_xor_sync(0xffffffffu, mx1, 1));
    mx1 = fmaxf(mx1, __shfl_xor_sync(0xffffffffu, mx1, 2));

    int t0 = tgt[grow0], t1 = tgt[grow1];
    float se0 = 0.f, se1 = 0.f, tv0 = -1e30f, tv1 = -1e30f;
    #pragma unroll
    for (int nt = 0; nt < 4; nt++) {
        int col = nt * 8 + 2 * tg;
        se0 += expf(L[nt][0] - mx0) + expf(L[nt][1] - mx0);
        se1 += expf(L[nt][2] - mx1) + expf(L[nt][3] - mx1);
        if (col == t0)     tv0 = L[nt][0];
        if (col + 1 == t0) tv0 = L[nt][1];
        if (col == t1)     tv1 = L[nt][2];
        if (col + 1 == t1) tv1 = L[nt][3];
    }
    se0 += __shfl_xor_sync(0xffffffffu, se0, 1);
    se0 += __shfl_xor_sync(0xffffffffu, se0, 2);
    se1 += __shfl_xor_sync(0xffffffffu, se1, 1);
    se1 += __shfl_xor_sync(0xffffffffu, se1, 2);
    tv0 = fmaxf(tv0, __shfl_xor_sync(0xffffffffu, tv0, 1));
    tv0 = fmaxf(tv0, __shfl_xor_sync(0xffffffffu, tv0, 2));
    tv1 = fmaxf(tv1, __shfl_xor_sync(0xffffffffu, tv1, 1));
    tv1 = fmaxf(tv1, __shfl_xor_sync(0xffffffffu, tv1, 2));

    if (tg == 0) {
        float nll0 = -(tv0 - mx0 - logf(se0));
        float nll1 = -(tv1 - mx1 - logf(se1));
        red[w * 8 + g] = nll0 + nll1;
    }
    __syncthreads();
    for (int s = 32; s > 0; s >>= 1) {
        if (tid < s) red[tid] += red[tid + s];
        __syncthreads();
    }
    if (tid == 0) g_losspart[blockIdx.x] = red[0];
}

__global__ void k_lossfin(float* out) {
    int tid = threadIdx.x;
    __shared__ float red[128];
    red[tid] = g_losspart[tid]; __syncthreads();
    for (int s = 64; s > 0; s >>= 1) {
        if (tid < s) red[tid] += red[tid + s];
        __syncthreads();
    }
    if (tid == 0) out[0] = red[0] / (float)TOK;
}

// ----------------------------- host driver -----------------------------------
extern "C" void kernel_launch(void* const* d_in, const int* in_sizes, int n_in,
                              void* d_out, int out_size) {
    const int*   idx = (const int*)  d_in[0];
    const int*   tgt = (const int*)  d_in[1];
    const float* emb = (const float*)d_in[2];
    const float* rms = (const float*)d_in[3];
    const float* Wq  = (const float*)d_in[4];
    const float* Wk  = (const float*)d_in[5];
    const float* Wv  = (const float*)d_in[6];
    const float* inw = (const float*)d_in[7];
    const float* inb = (const float*)d_in[8];
    const float* opw = (const float*)d_in[9];
    const float* opb = (const float*)d_in[10];
    const float* lw  = (const float*)d_in[11];
    const float* lb  = (const float*)d_in[12];
    const float* ow  = (const float*)d_in[13];
    const float* ob  = (const float*)d_in[14];
    float* out = (float*)d_out;

    float *x0, *x1;
    uint32_t *qh, *kh, *vh;
    cudaGetSymbolAddress((void**)&x0,  g_x0);
    cudaGetSymbolAddress((void**)&x1,  g_x1);
    cudaGetSymbolAddress((void**)&qh,  g_qh);
    cudaGetSymbolAddress((void**)&kh,  g_kh);
    cudaGetSymbolAddress((void**)&vh,  g_vh);

    const int SM64  = (64 + 128) * P * 4 + 512 + 512;
    const int SMM   = 4 * 128 * P * 4 + 512 + 128 + 256;
    cudaFuncSetAttribute(k_qkv,   cudaFuncAttributeMaxDynamicSharedMemorySize, SM64);
    cudaFuncSetAttribute(k_oproj, cudaFuncAttributeMaxDynamicSharedMemorySize, SM64);
    cudaFuncSetAttribute(k_mlp,   cudaFuncAttributeMaxDynamicSharedMemorySize, SMM);

    k_prep<<<(WROWS*64 + 255)/256, 256>>>(Wq, Wk, Wv, inw, opw, lw, ow);
    k_embed<<<dim3(Bb, 136), 256>>>(idx, emb);
    k_qkv<<<dim3(256, 3), 128, SM64>>>(x0, rms, inb, qh, kh, vh);
    k_attn_mma<<<1024, 256>>>();
    k_oproj<<<256, 128, SM64>>>(opb, x0, rms, x1);
    k_mlp<<<128, 256, SMM>>>(x1, rms, lb, ob, tgt, out);
    if (out_size > TOK*Vv) k_lossfin<<<1, 128>>>(out + (size_t)TOK*Vv);
}

// round 17
// speedup vs baseline: 1.0441x; 1.0441x over previous
#include <cuda_runtime.h>
#include <cuda_bf16.h>
#include <math.h>
#include <stdint.h>

#define Bb 8
#define Mm 2048
#define Dd 128
#define HDIM 16
#define Vv 32
#define TOK (Bb*Mm)          // 16384
#define P 68                 // smem word pitch for GEMM planes
#define KP 12                // smem word pitch for attention K/V tiles
#define ONES 0x3F803F80u     // bf16x2 (1.0, 1.0)

#define OFF_IN 384
#define OFF_OP 768
#define OFF_LW 896
#define OFF_OW 1024
#define WROWS 1056

// ----------------------------- scratch ---------------------------------------
__device__ float g_x0[TOK*Dd];
__device__ float g_x1[TOK*Dd];
__device__ uint32_t g_wh[WROWS*64];   // pre-packed bf16 hi planes (all weights)
__device__ uint32_t g_wlo[160*64];    // lo planes for lw (128 rows) + ow (32 rows)
__device__ uint32_t g_ath[TOK*64];    // attention out, packed bf16 pairs
__device__ uint32_t g_qh[TOK*64];     // Q pre-scaled by EXPC
__device__ uint32_t g_kh[TOK*64];
__device__ uint32_t g_vh[TOK*64];
__device__ float g_cos[Mm*64];
__device__ float g_sin[Mm*64];
__device__ float g_part[Bb*128];
__device__ float g_part2[256];
__device__ float g_losspart[128];

// ----------------------------- helpers ----------------------------------------
__device__ __forceinline__ uint32_t s_addr(const void* p) {
    uint32_t a;
    asm("{ .reg .u64 t; cvta.to.shared.u64 t, %1; cvt.u32.u64 %0, t; }"
        : "=r"(a) : "l"(p));
    return a;
}
__device__ __forceinline__ void cpa16(uint32_t saddr, const void* g) {
    asm volatile("cp.async.ca.shared.global [%0], [%1], 16;"
                 :: "r"(saddr), "l"(g));
}
#define CPA_COMMIT asm volatile("cp.async.commit_group;")
#define CPA_WAIT   asm volatile("cp.async.wait_group 0;" ::: "memory")

__device__ __forceinline__ void ldsm4(uint32_t r[4], uint32_t addr) {
    asm volatile("ldmatrix.sync.aligned.m8n8.x4.shared.b16 {%0,%1,%2,%3}, [%4];"
        : "=r"(r[0]), "=r"(r[1]), "=r"(r[2]), "=r"(r[3]) : "r"(addr));
}
__device__ __forceinline__ void ldsm4t(uint32_t r[4], uint32_t addr) {
    asm volatile("ldmatrix.sync.aligned.m8n8.x4.trans.shared.b16 {%0,%1,%2,%3}, [%4];"
        : "=r"(r[0]), "=r"(r[1]), "=r"(r[2]), "=r"(r[3]) : "r"(addr));
}
__device__ __forceinline__ void mma_bf16(float c[4], const uint32_t a[4],
                                         uint32_t b0, uint32_t b1) {
    asm volatile(
        "mma.sync.aligned.m16n8k16.row.col.f32.bf16.bf16.f32 "
        "{%0,%1,%2,%3}, {%4,%5,%6,%7}, {%8,%9}, {%0,%1,%2,%3};"
        : "+f"(c[0]), "+f"(c[1]), "+f"(c[2]), "+f"(c[3])
        : "r"(a[0]), "r"(a[1]), "r"(a[2]), "r"(a[3]), "r"(b0), "r"(b1));
}
__device__ __forceinline__ void bf16_split2(float x, float y,
                                            uint32_t& hi, uint32_t& lo) {
    __nv_bfloat162 hb = __float22bfloat162_rn(make_float2(x, y));
    float2 back = __bfloat1622float2(hb);
    __nv_bfloat162 lb = __float22bfloat162_rn(make_float2(x - back.x, y - back.y));
    hi = *(uint32_t*)&hb;
    lo = *(uint32_t*)&lb;
}
__device__ __forceinline__ uint32_t bf16_pack2(float x, float y) {
    __nv_bfloat162 hb = __float22bfloat162_rn(make_float2(x, y));
    return *(uint32_t*)&hb;
}
__device__ __forceinline__ float2 bf2_unpack(uint32_t w) {
    __nv_bfloat162 t;
    *(uint32_t*)&t = w;
    return __bfloat1622float2(t);
}
__device__ __forceinline__ void stage4(uint32_t* H, uint32_t* L, int idx,
                                       float a, float b, float c, float d) {
    uint32_t h0, l0, h1, l1;
    bf16_split2(a, b, h0, l0);
    bf16_split2(c, d, h1, l1);
    H[idx] = h0; H[idx + 1] = h1;
    L[idx] = l0; L[idx + 1] = l1;
}
__device__ __forceinline__ void stageH(uint32_t* H, int idx,
                                       float a, float b, float c, float d) {
    H[idx]     = bf16_pack2(a, b);
    H[idx + 1] = bf16_pack2(c, d);
}
#define EXPC 0.36067376022224085f
__device__ __forceinline__ float pexp(float t) {
    float r; asm("ex2.approx.f32 %0, %1;" : "=f"(r) : "f"(t));
    return r;
}

#define MMA6(accE, accO, ah, al, bh, bl)            \
    do {                                            \
        mma_bf16(accE, ah, (bh)[0], (bh)[2]);       \
        mma_bf16(accE, al, (bh)[0], (bh)[2]);       \
        mma_bf16(accE, ah, (bl)[0], (bl)[2]);       \
        mma_bf16(accO, ah, (bh)[1], (bh)[3]);       \
        mma_bf16(accO, al, (bh)[1], (bh)[3]);       \
        mma_bf16(accO, ah, (bl)[1], (bl)[3]);       \
    } while (0)

#define MMA2(accE, accO, ah, bh)                    \
    do {                                            \
        mma_bf16(accE, ah, (bh)[0], (bh)[2]);       \
        mma_bf16(accO, ah, (bh)[1], (bh)[3]);       \
    } while (0)

// =============================================================================
// Fused embed (+ssq partials) + RoPE tables + weight pre-pack. grid (8, 169)
// =============================================================================
__global__ void __launch_bounds__(256) k_embed(
    const int* __restrict__ idx, const float* __restrict__ emb,
    const float* __restrict__ Wq, const float* __restrict__ Wk,
    const float* __restrict__ Wv, const float* __restrict__ inw,
    const float* __restrict__ opw, const float* __restrict__ lw,
    const float* __restrict__ ow)
{
    int tid = threadIdx.x;
    if (blockIdx.y >= 136) {
        // ---- weight pre-pack: 264 blocks cover WROWS*64 = 67584 words exactly
        int pid = (blockIdx.y - 136) * 8 + blockIdx.x;
        int wid = pid * 256 + tid;
        if (wid >= WROWS * 64) return;
        int row = wid >> 6, col = wid & 63;
        const float* src;
        int r = row;
        if      (r < 128)  { src = Wq; }
        else if (r < 256)  { src = Wk;  r -= 128; }
        else if (r < 384)  { src = Wv;  r -= 256; }
        else if (r < 768)  { src = inw; r -= 384; }
        else if (r < 896)  { src = opw; r -= 768; }
        else if (r < 1024) { src = lw;  r -= 896; }
        else               { src = ow;  r -= 1024; }
        float2 v = *(const float2*)(src + (size_t)r * 128 + col * 2);
        if (row < OFF_LW) {
            g_wh[wid] = bf16_pack2(v.x, v.y);
        } else {
            uint32_t h, l;
            bf16_split2(v.x, v.y, h, l);
            g_wh[wid] = h;
            g_wlo[(size_t)(row - OFF_LW) * 64 + col] = l;
        }
        return;
    }
    if (blockIdx.y >= 128) {
        // ---- rope tables (powf hoisted)
        int rb = blockIdx.x * 8 + (blockIdx.y - 128);
        int i = tid & 63;
        int pos0 = rb * 32 + (tid >> 6);
        float base = powf(10000.0f, -2.0f * ((float)i - 1.0f) / 128.0f);
        #pragma unroll
        for (int e = 0; e < 8; e++) {
            int pos = pos0 + e * 4;
            float ang = (float)pos * base;
            float s, c;
            sincosf(ang, &s, &c);
            g_cos[pos * 64 + i] = c;
            g_sin[pos * 64 + i] = s;
        }
        return;
    }
    int b   = blockIdx.x;
    int seg = blockIdx.y;
    int tok0 = seg * 16;
    float ss = 0.f;
    #pragma unroll
    for (int e = 0; e < 8; e++) {
        int li = tid + e * 256;
        int t  = tok0 + (li >> 7);
        int d  = li & 127;
        int row = idx[b*Mm + t];
        float vv = emb[row*Dd + d];
        g_x0[((size_t)(b*Mm + t))*Dd + d] = vv;
        ss += vv * vv;
    }
    __shared__ float red[256];
    red[tid] = ss; __syncthreads();
    for (int s = 128; s > 0; s >>= 1) {
        if (tid < s) red[tid] += red[tid + s];
        __syncthreads();
    }
    if (tid == 0) g_part[b*128 + seg] = red[0];
}

__device__ __forceinline__ void inv_reduce(const float* part, int bb,
                                           int lane, float* sinv) {
    float v = part[bb*128 + lane]      + part[bb*128 + lane + 32]
            + part[bb*128 + lane + 64] + part[bb*128 + lane + 96];
    #pragma unroll
    for (int off = 16; off; off >>= 1) v += __shfl_xor_sync(0xffffffffu, v, off);
    if (lane == 0) *sinv = 512.0f / sqrtf(v);
}

// =============================================================================
// Fused QKV — 64-row CTAs, 128 threads, 3 CTAs/SM. grid (256, 3)
// =============================================================================
__global__ void __launch_bounds__(128, 3) k_qkv(
    const float* __restrict__ x0, const float* __restrict__ rms,
    const float* __restrict__ inb,
    uint32_t* __restrict__ qh_, uint32_t* __restrict__ kh_,
    uint32_t* __restrict__ vh_)
{
    extern __shared__ uint32_t smw[];
    uint32_t* Ah = smw;
    uint32_t* Wh = Ah + 64 * P;
    float* bias_s = (float*)(Wh + 128 * P);
    __shared__ float sinv;

    int which = blockIdx.y;
    uint32_t* Oh = (which == 0) ? qh_ : ((which == 1) ? kh_ : vh_);
    const uint32_t* W1 = g_wh + (size_t)(which * 128) * 64;
    const uint32_t* W2 = g_wh + (size_t)(OFF_IN + which * 128) * 64;
    float oscale = (which == 0) ? EXPC : 1.0f;

    int tid = threadIdx.x;
    int rowBase = blockIdx.x * 64;
    if (tid < 32) inv_reduce(g_part, rowBase >> 11, tid, &sinv);
    bias_s[tid] = inb[which * 128 + tid];

    uint32_t sAh = s_addr(Ah), sWh = s_addr(Wh);

    #pragma unroll
    for (int i = 0; i < 16; i++) {
        int f = tid + i * 128;
        int row = f >> 4, c = (f & 15) * 4;
        cpa16(sWh + ((uint32_t)row * P + c) * 4, W1 + (size_t)row * 64 + c);
    }
    CPA_COMMIT;
    __syncthreads();
    float inv = sinv;

    #pragma unroll
    for (int i = 0; i < 16; i++) {
        int f = tid + i * 128;
        int row = f >> 5, q4 = f & 31;
        int m = (rowBase + row) & (Mm - 1);
        float4 xv = *(const float4*)(x0 + (size_t)(rowBase + row) * 128 + q4 * 4);
        float4 sv = *(const float4*)(rms + (size_t)m * 128 + q4 * 4);
        stageH(Ah, row * P + q4 * 2,
               xv.x * inv * sv.x, xv.y * inv * sv.y,
               xv.z * inv * sv.z, xv.w * inv * sv.w);
    }
    CPA_WAIT;
    __syncthreads();

    int w = tid >> 5, lane = tid & 31, g = lane >> 2, tg = lane & 3;
    int r0 = w * 16 + g, r1 = r0 + 8;
    int lrow = lane & 15;
    int lcol = (lane >> 4) * 4;
    uint32_t aoff = ((uint32_t)(w * 16 + lrow) * P + lcol) * 4;
    uint32_t boff = ((uint32_t)lrow * P + lcol) * 4;
    uint32_t adA = sAh + aoff;
    uint32_t adW = sWh + boff;

    float acc[16][4];
    #pragma unroll
    for (int nt = 0; nt < 16; nt++)
        #pragma unroll
        for (int e = 0; e < 4; e++) acc[nt][e] = 0.f;

    #pragma unroll
    for (int kg = 0; kg < 8; kg++) {
        uint32_t ah[4];
        ldsm4(ah, adA + kg * 32);
        #pragma unroll
        for (int ntp = 0; ntp < 8; ntp++) {
            uint32_t bh[4];
            ldsm4(bh, adW + (uint32_t)ntp * (16 * P * 4) + kg * 32);
            MMA2(acc[2*ntp], acc[2*ntp+1], ah, bh);
        }
    }

    int m0 = (rowBase + r0) & (Mm - 1), m1 = (rowBase + r1) & (Mm - 1);
    #pragma unroll
    for (int nt = 0; nt < 16; nt++) {
        int i = nt * 4 + tg;
        float c0 = g_cos[m0 * 64 + i], s0 = g_sin[m0 * 64 + i];
        float c1 = g_cos[m1 * 64 + i], s1 = g_sin[m1 * 64 + i];
        float te = acc[nt][0], to = acc[nt][1];
        acc[nt][0] =  te * c0 + to * s0;
        acc[nt][1] = -te * s0 + to * c0;
        te = acc[nt][2]; to = acc[nt][3];
        acc[nt][2] =  te * c1 + to * s1;
        acc[nt][3] = -te * s1 + to * c1;
    }

    uint32_t a2h[8][4];
    #pragma unroll
    for (int kg = 0; kg < 8; kg++) {
        a2h[kg][0] = bf16_pack2(acc[2*kg][0],   acc[2*kg][1]);
        a2h[kg][1] = bf16_pack2(acc[2*kg][2],   acc[2*kg][3]);
        a2h[kg][2] = bf16_pack2(acc[2*kg+1][0], acc[2*kg+1][1]);
        a2h[kg][3] = bf16_pack2(acc[2*kg+1][2], acc[2*kg+1][3]);
    }
    __syncthreads();

    #pragma unroll
    for (int i = 0; i < 16; i++) {
        int f = tid + i * 128;
        int row = f >> 4, c = (f & 15) * 4;
        cpa16(sWh + ((uint32_t)row * P + c) * 4, W2 + (size_t)row * 64 + c);
    }
    CPA_COMMIT; CPA_WAIT;
    __syncthreads();

    #pragma unroll
    for (int nt = 0; nt < 16; nt++)
        #pragma unroll
        for (int e = 0; e < 4; e++) acc[nt][e] = 0.f;

    #pragma unroll
    for (int kg = 0; kg < 8; kg++) {
        #pragma unroll
        for (int ntp = 0; ntp < 8; ntp++) {
            uint32_t bh[4];
            ldsm4(bh, adW + (uint32_t)ntp * (16 * P * 4) + kg * 32);
            MMA2(acc[2*ntp], acc[2*ntp+1], a2h[kg], bh);
        }
    }

    int grow0 = rowBase + r0, grow1 = rowBase + r1;
    #pragma unroll
    for (int nt = 0; nt < 16; nt++) {
        int col = nt * 8 + 2 * tg;
        float v0 = (acc[nt][0] + bias_s[col])     * oscale;
        float v1 = (acc[nt][1] + bias_s[col + 1]) * oscale;
        float v2 = (acc[nt][2] + bias_s[col])     * oscale;
        float v3 = (acc[nt][3] + bias_s[col + 1]) * oscale;
        Oh[(size_t)grow0 * 64 + nt * 4 + tg] = bf16_pack2(v0, v1);
        Oh[(size_t)grow1 * 64 + nt * 4 + tg] = bf16_pack2(v2, v3);
    }
}

// =============================================================================
// Flash attention — fused S->P per ntp (low live regs), 4 CTAs/SM target.
// =============================================================================
__device__ __forceinline__ void attn_load_tile(uint32_t* KVbuf, int tokbase,
                                               int h, int kb, int tid) {
    #pragma unroll
    for (int i = 0; i < 2; i++) {
        int s = tid + i * 256;
        int arr = s >> 8;
        int rem = s & 255;
        int key = rem >> 1, hf = rem & 1;
        const uint32_t* src = (arr == 0) ? g_kh : g_vh;
        src += (size_t)(tokbase + kb + key) * 64 + h * 8 + hf * 4;
        cpa16(s_addr(KVbuf + arr * (128 * KP) + key * KP + hf * 4), src);
    }
    CPA_COMMIT;
}

__global__ void __launch_bounds__(256, 4) k_attn_mma() {
    int bid = blockIdx.x;
    int qt = 15 - (bid >> 6);
    int bh = bid & 63;
    int b = bh >> 3, h = bh & 7;
    int tid = threadIdx.x;
    int w = tid >> 5, lane = tid & 31;
    int g = lane >> 2, tg = lane & 3;
    int tokbase = b * Mm;
    int qBase = qt * 128 + w * 16;
    int diag = qBase >> 6;

    __shared__ __align__(16) uint32_t KV[2][2 * 128 * KP];

    uint32_t qh[4];
    {
        const uint32_t* ph = g_qh + (size_t)(tokbase + qBase) * 64 + h * 8;
        qh[0] = ph[(size_t)g * 64 + tg];
        qh[1] = ph[(size_t)(g + 8) * 64 + tg];
        qh[2] = ph[(size_t)g * 64 + tg + 4];
        qh[3] = ph[(size_t)(g + 8) * 64 + tg + 4];
    }

    int lrow = lane & 15;
    int lcol = (lane >> 4) * 4;
    uint32_t kvoff = ((uint32_t)lrow * KP + lcol) * 4;

    float o[2][4];
    #pragma unroll
    for (int t = 0; t < 2; t++)
        #pragma unroll
        for (int e = 0; e < 4; e++) o[t][e] = 0.f;
    float lacc[4] = {0.f, 0.f, 0.f, 0.f};

    int q0 = qBase + g;
    int q1 = qBase + g + 8;

    int nkt = qt + 1;
    attn_load_tile(KV[0], tokbase, h, 0, tid);

    for (int kt = 0; kt < nkt; kt++) {
        int buf = kt & 1;
        CPA_WAIT;
        __syncthreads();
        if (kt + 1 < nkt) attn_load_tile(KV[buf ^ 1], tokbase, h, (kt + 1) * 128, tid);
        uint32_t base = s_addr(KV[buf]);

        #pragma unroll
        for (int half = 0; half < 2; half++) {
            int j2 = kt * 2 + half;
            if (j2 > diag) continue;
            uint32_t adK = base + (uint32_t)half * (64 * KP * 4) + kvoff;
            uint32_t adV = base + (128 * KP * 4) + (uint32_t)half * (64 * KP * 4) + kvoff;

            uint32_t pk[8][2];
            if (j2 < diag) {
                // mask-free: fused mma -> exp -> pack per ntp (small live set)
                #pragma unroll
                for (int ntp = 0; ntp < 4; ntp++) {
                    uint32_t bh_[4];
                    ldsm4(bh_, adK + (uint32_t)ntp * (16 * KP * 4));
                    float s0[4] = {0.f, 0.f, 0.f, 0.f};
                    float s1[4] = {0.f, 0.f, 0.f, 0.f};
                    mma_bf16(s0, qh, bh_[0], bh_[2]);
                    mma_bf16(s1, qh, bh_[1], bh_[3]);
                    pk[2*ntp][0]   = bf16_pack2(pexp(s0[0]), pexp(s0[1]));
                    pk[2*ntp][1]   = bf16_pack2(pexp(s0[2]), pexp(s0[3]));
                    pk[2*ntp+1][0] = bf16_pack2(pexp(s1[0]), pexp(s1[1]));
                    pk[2*ntp+1][1] = bf16_pack2(pexp(s1[2]), pexp(s1[3]));
                }
            } else {
                int kbd = j2 * 64;
                #pragma unroll
                for (int ntp = 0; ntp < 4; ntp++) {
                    uint32_t bh_[4];
                    ldsm4(bh_, adK + (uint32_t)ntp * (16 * KP * 4));
                    float s0[4] = {0.f, 0.f, 0.f, 0.f};
                    float s1[4] = {0.f, 0.f, 0.f, 0.f};
                    mma_bf16(s0, qh, bh_[0], bh_[2]);
                    mma_bf16(s1, qh, bh_[1], bh_[3]);
                    int kc0 = kbd + (2*ntp) * 8 + 2 * tg;
                    int kc1 = kc0 + 8;
                    float t0 = (kc0     <= q0) ? s0[0] : -1e30f;
                    float t1 = (kc0 + 1 <= q0) ? s0[1] : -1e30f;
                    float t2 = (kc0     <= q1) ? s0[2] : -1e30f;
                    float t3 = (kc0 + 1 <= q1) ? s0[3] : -1e30f;
                    pk[2*ntp][0] = bf16_pack2(pexp(t0), pexp(t1));
                    pk[2*ntp][1] = bf16_pack2(pexp(t2), pexp(t3));
                    t0 = (kc1     <= q0) ? s1[0] : -1e30f;
                    t1 = (kc1 + 1 <= q0) ? s1[1] : -1e30f;
                    t2 = (kc1     <= q1) ? s1[2] : -1e30f;
                    t3 = (kc1 + 1 <= q1) ? s1[3] : -1e30f;
                    pk[2*ntp+1][0] = bf16_pack2(pexp(t0), pexp(t1));
                    pk[2*ntp+1][1] = bf16_pack2(pexp(t2), pexp(t3));
                }
            }

            #pragma unroll
            for (int kg = 0; kg < 4; kg++) {
                uint32_t ah[4] = { pk[2*kg][0], pk[2*kg][1], pk[2*kg+1][0], pk[2*kg+1][1] };
                uint32_t bh_[4];
                ldsm4t(bh_, adV + (uint32_t)kg * (16 * KP * 4));
                mma_bf16(o[0], ah, bh_[0], bh_[1]);
                mma_bf16(o[1], ah, bh_[2], bh_[3]);
                mma_bf16(lacc, ah, ONES, ONES);
            }
        }
    }

    float i0 = 1.f / lacc[0], i1 = 1.f / lacc[2];

    #pragma unroll
    for (int t = 0; t < 2; t++) {
        int wrd = h * 8 + t * 4 + tg;
        g_ath[(size_t)(tokbase + q0) * 64 + wrd] = bf16_pack2(o[t][0] * i0, o[t][1] * i0);
        g_ath[(size_t)(tokbase + q1) * 64 + wrd] = bf16_pack2(o[t][2] * i1, o[t][3] * i1);
    }
}

// =============================================================================
// Fused out_proj — unchanged (round 15)
// =============================================================================
__global__ void __launch_bounds__(128, 3) k_oproj(
    const float* __restrict__ opb, const float* __restrict__ x0,
    const float* __restrict__ rms, float* __restrict__ x1)
{
    extern __shared__ uint32_t smw[];
    uint32_t* Ah = smw;
    uint32_t* Wh = Ah + 64 * P;
    float* bias_s = (float*)(Wh + 128 * P);
    float* red = bias_s + 128;
    __shared__ float sinv;

    int tid = threadIdx.x;
    int rowBase = blockIdx.x * 64;
    if (tid < 32) inv_reduce(g_part, rowBase >> 11, tid, &sinv);
    bias_s[tid] = opb[tid];

    uint32_t sAh = s_addr(Ah), sWh = s_addr(Wh);
    const uint32_t* Wsrc = g_wh + (size_t)OFF_OP * 64;

    #pragma unroll
    for (int i = 0; i < 8; i++) {
        int f = tid + i * 128;
        int row = f >> 4, c = (f & 15) * 4;
        cpa16(sAh + ((uint32_t)row * P + c) * 4,
              g_ath + (size_t)(rowBase + row) * 64 + c);
    }
    #pragma unroll
    for (int i = 0; i < 16; i++) {
        int f = tid + i * 128;
        int row = f >> 4, c = (f & 15) * 4;
        cpa16(sWh + ((uint32_t)row * P + c) * 4, Wsrc + (size_t)row * 64 + c);
    }
    CPA_COMMIT; CPA_WAIT;
    __syncthreads();
    float inv = sinv;

    int w = tid >> 5, lane = tid & 31, g = lane >> 2, tg = lane & 3;
    int r0 = w * 16 + g, r1 = r0 + 8;
    int lrow = lane & 15;
    int lcol = (lane >> 4) * 4;
    uint32_t aoff = ((uint32_t)(w * 16 + lrow) * P + lcol) * 4;
    uint32_t boff = ((uint32_t)lrow * P + lcol) * 4;
    uint32_t adA = sAh + aoff;
    uint32_t adW = sWh + boff;

    float acc[16][4];
    #pragma unroll
    for (int nt = 0; nt < 16; nt++)
        #pragma unroll
        for (int e = 0; e < 4; e++) acc[nt][e] = 0.f;

    #pragma unroll
    for (int kg = 0; kg < 8; kg++) {
        uint32_t ah[4];
        ldsm4(ah, adA + kg * 32);
        #pragma unroll
        for (int ntp = 0; ntp < 8; ntp++) {
            uint32_t bh[4];
            ldsm4(bh, adW + (uint32_t)ntp * (16 * P * 4) + kg * 32);
            MMA2(acc[2*ntp], acc[2*ntp+1], ah, bh);
        }
    }

    int grow0 = rowBase + r0, grow1 = rowBase + r1;
    int m0 = grow0 & (Mm - 1), m1 = grow1 & (Mm - 1);
    float ssq = 0.f;
    #pragma unroll
    for (int nt = 0; nt < 16; nt++) {
        int col = nt * 8 + 2 * tg;
        float2 xa = *(const float2*)(x0 + (size_t)grow0 * 128 + col);
        float2 sa = *(const float2*)(rms + (size_t)m0 * 128 + col);
        float2 xb = *(const float2*)(x0 + (size_t)grow1 * 128 + col);
        float2 sb = *(const float2*)(rms + (size_t)m1 * 128 + col);
        float v0 = acc[nt][0] + bias_s[col]     + xa.x * inv * sa.x;
        float v1 = acc[nt][1] + bias_s[col + 1] + xa.y * inv * sa.y;
        float v2 = acc[nt][2] + bias_s[col]     + xb.x * inv * sb.x;
        float v3 = acc[nt][3] + bias_s[col + 1] + xb.y * inv * sb.y;
        float2 o0; o0.x = v0; o0.y = v1;
        float2 o1; o1.x = v2; o1.y = v3;
        *(float2*)(x1 + (size_t)grow0 * 128 + col) = o0;
        *(float2*)(x1 + (size_t)grow1 * 128 + col) = o1;
        ssq += v0 * v0 + v1 * v1 + v2 * v2 + v3 * v3;
    }

    red[tid] = ssq;
    __syncthreads();
    for (int s = 64; s > 0; s >>= 1) {
        if (tid < s) red[tid] += red[tid + s];
        __syncthreads();
    }
    if (tid == 0) g_part2[blockIdx.x] = red[0];
}

// =============================================================================
// Fused MLP + logits + loss partials (3-term; weights via pre-packed planes)
// =============================================================================
__global__ void __launch_bounds__(256, 1) k_mlp(
    const float* __restrict__ x1, const float* __restrict__ rms,
    const float* __restrict__ lb, const float* __restrict__ ob,
    const int* __restrict__ tgt, float* __restrict__ out)
{
    extern __shared__ uint32_t smw[];
    uint32_t* Ah = smw;
    uint32_t* Al = Ah + 128 * P;
    uint32_t* Wh = Al + 128 * P;
    uint32_t* Wl = Wh + 128 * P;
    float* biasl = (float*)(Wl + 128 * P);
    float* biaso = biasl + 128;
    float* red   = biaso + 32;
    __shared__ float sinv;

    int tid = threadIdx.x;
    int rowBase = blockIdx.x * 128;
    int lane = tid & 31;
    if (tid < 32) {
        int bb = rowBase >> 11;
        float v = g_part2[bb * 32 + lane];
        #pragma unroll
        for (int off = 16; off; off >>= 1) v += __shfl_xor_sync(0xffffffffu, v, off);
        if (lane == 0) sinv = 512.0f / sqrtf(v);
    }
    if (tid < 128) biasl[tid] = lb[tid];
    if (tid >= 128 && tid < 160) biaso[tid - 128] = ob[tid - 128];

    uint32_t sAh = s_addr(Ah), sAl = s_addr(Al);
    uint32_t sWh = s_addr(Wh), sWl = s_addr(Wl);

    {
        const uint32_t* srcWh = g_wh + (size_t)OFF_LW * 64;
        const uint32_t* srcWl = g_wlo;
        #pragma unroll
        for (int i = 0; i < 8; i++) {
            int f = tid + i * 256;
            int row = f >> 4, c = (f & 15) * 4;
            uint32_t so = ((uint32_t)row * P + c) * 4;
            size_t go = (size_t)row * 64 + c;
            cpa16(sWh + so, srcWh + go);
            cpa16(sWl + so, srcWl + go);
        }
        CPA_COMMIT;
    }
    __syncthreads();
    float inv = sinv;

    #pragma unroll
    for (int i = 0; i < 16; i++) {
        int f = tid + i * 256;
        int row = f >> 5, q4 = f & 31;
        int m = (rowBase + row) & (Mm - 1);
        float4 xv = *(const float4*)(x1 + (size_t)(rowBase + row) * 128 + q4 * 4);
        float4 sv = *(const float4*)(rms + (size_t)m * 128 + q4 * 4);
        stage4(Ah, Al, row * P + q4 * 2,
               xv.x * inv * sv.x, xv.y * inv * sv.y,
               xv.z * inv * sv.z, xv.w * inv * sv.w);
    }
    CPA_WAIT;
    __syncthreads();

    int w = tid >> 5, g = lane >> 2, tg = lane & 3;
    int r0 = w * 16 + g, r1 = r0 + 8;
    int lrow = lane & 15;
    int lcol = (lane >> 4) * 4;
    uint32_t aoff = ((uint32_t)(w * 16 + lrow) * P + lcol) * 4;
    uint32_t boff = ((uint32_t)lrow * P + lcol) * 4;
    uint32_t adA_h = sAh + aoff, adA_l = sAl + aoff;
    uint32_t adW_h = sWh + boff, adW_l = sWl + boff;

    float acc[16][4];
    #pragma unroll
    for (int nt = 0; nt < 16; nt++)
        #pragma unroll
        for (int e = 0; e < 4; e++) acc[nt][e] = 0.f;

    #pragma unroll
    for (int kg = 0; kg < 8; kg++) {
        uint32_t ah[4], al[4];
        ldsm4(ah, adA_h + kg * 32);
        ldsm4(al, adA_l + kg * 32);
        #pragma unroll
        for (int ntp = 0; ntp < 8; ntp++) {
            uint32_t bh[4], bl[4];
            ldsm4(bh, adW_h + (uint32_t)ntp * (16 * P * 4) + kg * 32);
            ldsm4(bl, adW_l + (uint32_t)ntp * (16 * P * 4) + kg * 32);
            MMA6(acc[2*ntp], acc[2*ntp+1], ah, al, bh, bl);
        }
    }

    #pragma unroll
    for (int nt = 0; nt < 16; nt++) {
        int wrd = nt * 4 + tg;
        int col = nt * 8 + 2 * tg;
        float2 x2a_h = bf2_unpack(Ah[r0 * P + wrd]);
        float2 x2a_l = bf2_unpack(Al[r0 * P + wrd]);
        float2 x2b_h = bf2_unpack(Ah[r1 * P + wrd]);
        float2 x2b_l = bf2_unpack(Al[r1 * P + wrd]);
        acc[nt][0] = (x2a_h.x + x2a_l.x) + fmaxf(acc[nt][0] + biasl[col],     0.f);
        acc[nt][1] = (x2a_h.y + x2a_l.y) + fmaxf(acc[nt][1] + biasl[col + 1], 0.f);
        acc[nt][2] = (x2b_h.x + x2b_l.x) + fmaxf(acc[nt][2] + biasl[col],     0.f);
        acc[nt][3] = (x2b_h.y + x2b_l.y) + fmaxf(acc[nt][3] + biasl[col + 1], 0.f);
    }

    uint32_t a2h[8][4], a2l[8][4];
    #pragma unroll
    for (int kg = 0; kg < 8; kg++) {
        bf16_split2(acc[2*kg][0],   acc[2*kg][1],   a2h[kg][0], a2l[kg][0]);
        bf16_split2(acc[2*kg][2],   acc[2*kg][3],   a2h[kg][1], a2l[kg][1]);
        bf16_split2(acc[2*kg+1][0], acc[2*kg+1][1], a2h[kg][2], a2l[kg][2]);
        bf16_split2(acc[2*kg+1][2], acc[2*kg+1][3], a2h[kg][3], a2l[kg][3]);
    }
    __syncthreads();

    {
        const uint32_t* srcOh = g_wh + (size_t)OFF_OW * 64;
        const uint32_t* srcOl = g_wlo + (size_t)128 * 64;
        #pragma unroll
        for (int i = 0; i < 2; i++) {
            int f = tid + i * 256;
            int row = f >> 4, c = (f & 15) * 4;
            uint32_t so = ((uint32_t)row * P + c) * 4;
            size_t go = (size_t)row * 64 + c;
            cpa16(sWh + so, srcOh + go);
            cpa16(sWl + so, srcOl + go);
        }
        CPA_COMMIT; CPA_WAIT;
    }
    __syncthreads();

    int grow0 = rowBase + r0, grow1 = rowBase + r1;
    float L[4][4];
    #pragma unroll
    for (int nt = 0; nt < 4; nt++)
        #pragma unroll
        for (int e = 0; e < 4; e++) L[nt][e] = 0.f;

    #pragma unroll
    for (int kg = 0; kg < 8; kg++) {
        #pragma unroll
        for (int ntp = 0; ntp < 2; ntp++) {
            uint32_t bh[4], bl[4];
            ldsm4(bh, adW_h + (uint32_t)ntp * (16 * P * 4) + kg * 32);
            ldsm4(bl, adW_l + (uint32_t)ntp * (16 * P * 4) + kg * 32);
            MMA6(L[2*ntp], L[2*ntp+1], a2h[kg], a2l[kg], bh, bl);
        }
    }

    #pragma unroll
    for (int nt = 0; nt < 4; nt++) {
        int col = nt * 8 + 2 * tg;
        L[nt][0] += biaso[col];
        L[nt][1] += biaso[col + 1];
        L[nt][2] += biaso[col];
        L[nt][3] += biaso[col + 1];
        float2 o0; o0.x = L[nt][0]; o0.y = L[nt][1];
        float2 o1; o1.x = L[nt][2]; o1.y = L[nt][3];
        *(float2*)(out + (size_t)grow0 * 32 + col) = o0;
        *(float2*)(out + (size_t)grow1 * 32 + col) = o1;
    }

    float mx0 = -1e30f, mx1 = -1e30f;
    #pragma unroll
    for (int nt = 0; nt < 4; nt++) {
        mx0 = fmaxf(mx0, fmaxf(L[nt][0], L[nt][1]));
        mx1 = fmaxf(mx1, fmaxf(L[nt][2], L[nt][3]));
    }
    mx0 = fmaxf(mx0, __shfl_xor_sync(0xffffffffu, mx0, 1));
    mx0 = fmaxf(mx0, __shfl_xor_sync(0xffffffffu, mx0, 2));
    mx1 = fmaxf(mx1, __shfl_xor_sync(0xffffffffu, mx1, 1));
    mx1 = fmaxf(mx1, __shfl_xor_sync(0xffffffffu, mx1, 2));

    int t0 = tgt[grow0], t1 = tgt[grow1];
    float se0 = 0.f, se1 = 0.f, tv0 = -1e30f, tv1 = -1e30f;
    #pragma unroll
    for (int nt = 0; nt < 4; nt++) {
        int col = nt * 8 + 2 * tg;
        se0 += expf(L[nt][0] - mx0) + expf(L[nt][1] - mx0);
        se1 += expf(L[nt][2] - mx1) + expf(L[nt][3] - mx1);
        if (col == t0)     tv0 = L[nt][0];
        if (col + 1 == t0) tv0 = L[nt][1];
        if (col == t1)     tv1 = L[nt][2];
        if (col + 1 == t1) tv1 = L[nt][3];
    }
    se0 += __shfl_xor_sync(0xffffffffu, se0, 1);
    se0 += __shfl_xor_sync(0xffffffffu, se0, 2);
    se1 += __shfl_xor_sync(0xffffffffu, se1, 1);
    se1 += __shfl_xor_sync(0xffffffffu, se1, 2);
    tv0 = fmaxf(tv0, __shfl_xor_sync(0xffffffffu, tv0, 1));
    tv0 = fmaxf(tv0, __shfl_xor_sync(0xffffffffu, tv0, 2));
    tv1 = fmaxf(tv1, __shfl_xor_sync(0xffffffffu, tv1, 1));
    tv1 = fmaxf(tv1, __shfl_xor_sync(0xffffffffu, tv1, 2));

    if (tg == 0) {
        float nll0 = -(tv0 - mx0 - logf(se0));
        float nll1 = -(tv1 - mx1 - logf(se1));
        red[w * 8 + g] = nll0 + nll1;
    }
    __syncthreads();
    for (int s = 32; s > 0; s >>= 1) {
        if (tid < s) red[tid] += red[tid + s];
        __syncthreads();
    }
    if (tid == 0) g_losspart[blockIdx.x] = red[0];
}

__global__ void k_lossfin(float* out) {
    int tid = threadIdx.x;
    __shared__ float red[128];
    red[tid] = g_losspart[tid]; __syncthreads();
    for (int s = 64; s > 0; s >>= 1) {
        if (tid < s) red[tid] += red[tid + s];
        __syncthreads();
    }
    if (tid == 0) out[0] = red[0] / (float)TOK;
}

// ----------------------------- host driver -----------------------------------
extern "C" void kernel_launch(void* const* d_in, const int* in_sizes, int n_in,
                              void* d_out, int out_size) {
    const int*   idx = (const int*)  d_in[0];
    const int*   tgt = (const int*)  d_in[1];
    const float* emb = (const float*)d_in[2];
    const float* rms = (const float*)d_in[3];
    const float* Wq  = (const float*)d_in[4];
    const float* Wk  = (const float*)d_in[5];
    const float* Wv  = (const float*)d_in[6];
    const float* inw = (const float*)d_in[7];
    const float* inb = (const float*)d_in[8];
    const float* opw = (const float*)d_in[9];
    const float* opb = (const float*)d_in[10];
    const float* lw  = (const float*)d_in[11];
    const float* lb  = (const float*)d_in[12];
    const float* ow  = (const float*)d_in[13];
    const float* ob  = (const float*)d_in[14];
    float* out = (float*)d_out;

    float *x0, *x1;
    uint32_t *qh, *kh, *vh;
    cudaGetSymbolAddress((void**)&x0,  g_x0);
    cudaGetSymbolAddress((void**)&x1,  g_x1);
    cudaGetSymbolAddress((void**)&qh,  g_qh);
    cudaGetSymbolAddress((void**)&kh,  g_kh);
    cudaGetSymbolAddress((void**)&vh,  g_vh);

    const int SM64  = (64 + 128) * P * 4 + 512 + 512;
    const int SMM   = 4 * 128 * P * 4 + 512 + 128 + 256;
    cudaFuncSetAttribute(k_qkv,   cudaFuncAttributeMaxDynamicSharedMemorySize, SM64);
    cudaFuncSetAttribute(k_oproj, cudaFuncAttributeMaxDynamicSharedMemorySize, SM64);
    cudaFuncSetAttribute(k_mlp,   cudaFuncAttributeMaxDynamicSharedMemorySize, SMM);

    // embed + rope tables + weight pre-pack, all in one launch
    k_embed<<<dim3(Bb, 169), 256>>>(idx, emb, Wq, Wk, Wv, inw, opw, lw, ow);
    k_qkv<<<dim3(256, 3), 128, SM64>>>(x0, rms, inb, qh, kh, vh);
    k_attn_mma<<<1024, 256>>>();
    k_oproj<<<256, 128, SM64>>>(opb, x0, rms, x1);
    k_mlp<<<128, 256, SMM>>>(x1, rms, lb, ob, tgt, out);
    if (out_size > TOK*Vv) k_lossfin<<<1, 128>>>(out + (size_t)TOK*Vv);
}